// round 4
// baseline (speedup 1.0000x reference)
#include <cuda_runtime.h>
#include <cuda_fp16.h>
#include <math.h>

#define Hh 2048
#define Tt 4096
#define Dd 66
#define G4H (4*Hh)
#define NBLK 148
#define NTHR 672
#define NWARP (NTHR/32)
#define WELEM ((size_t)G4H*(size_t)Hh)
#define WSTRIDE ((size_t)Hh*(size_t)Hh)

// ---------------- persistent device state (static; no runtime allocs) -------
__device__ float  g_h1[2][Hh];
__device__ float  g_h2[2][Hh];
__device__ float  g_h2hist[Tt][Hh];                // 33.5 MB
__device__ __half g_pre1[(size_t)Tt * G4H];        // 67 MB fp16 (streamed, .cs)
__device__ __half g_whh1[WELEM];                   // 33.5 MB fp16 (L2-resident)
__device__ __half g_wih2[WELEM];
__device__ __half g_whh2[WELEM];

// flag barrier state (monotonic across graph replays)
__device__ volatile unsigned g_arrive[NBLK];
__device__ volatile unsigned g_release;

__device__ __forceinline__ float sigf(float x) { return 1.0f / (1.0f + expf(-x)); }

// ---------------- flag-based grid barrier -----------------------------------
__device__ __forceinline__ void gbar(unsigned target) {
    __syncthreads();
    if (blockIdx.x == 0) {
        if (threadIdx.x > 0 && threadIdx.x < NBLK) {
            while ((int)(g_arrive[threadIdx.x] - target) < 0) { }
        }
        __syncthreads();
        if (threadIdx.x == 0) { __threadfence(); g_release = target; }
    } else {
        if (threadIdx.x == 0) {
            __threadfence();
            g_arrive[blockIdx.x] = target;
            while ((int)(g_release - target) < 0) { }
            __threadfence();
        }
    }
    __syncthreads();
}

// ---------------- helpers ----------------------------------------------------
__device__ __forceinline__ float wreduce(float s) {
#pragma unroll
    for (int o = 16; o; o >>= 1) s += __shfl_down_sync(0xffffffffu, s, o);
    return s;
}

__device__ __forceinline__ float cvdot(uint2 u, float4 h) {
    float2 f0 = __half22float2(*reinterpret_cast<__half2*>(&u.x));
    float2 f1 = __half22float2(*reinterpret_cast<__half2*>(&u.y));
    return f0.x * h.x + f0.y * h.y + f1.x * h.z + f1.y * h.w;
}

// Dot of 4 fp16 weight rows (gate i/f/g/o of one hidden unit) against one fp32
// vector in smem. Weight uint2 loads coalesced (256B/warp/row); h float4 LDS
// conflict-free and shared across the 4 rows.
__device__ __forceinline__ float4 dot4rows(const __half* __restrict__ w0,
                                           const float4* __restrict__ hv,
                                           int lane) {
    const __half* w1 = w0 + WSTRIDE;
    const __half* w2 = w0 + 2 * WSTRIDE;
    const __half* w3 = w0 + 3 * WSTRIDE;
    float a0 = 0.f, a1 = 0.f, a2 = 0.f, a3 = 0.f;
#pragma unroll 8
    for (int k = 0; k < 16; k++) {
        int idx = k * 32 + lane;
        float4 h = hv[idx];
        a0 += cvdot(((const uint2*)w0)[idx], h);
        a1 += cvdot(((const uint2*)w1)[idx], h);
        a2 += cvdot(((const uint2*)w2)[idx], h);
        a3 += cvdot(((const uint2*)w3)[idx], h);
    }
    return make_float4(wreduce(a0), wreduce(a1), wreduce(a2), wreduce(a3));
}

// fp32 warp dot (proj kernel only)
__device__ __forceinline__ float warp_dot(const float4* __restrict__ w,
                                          const float4* __restrict__ sh,
                                          int lane) {
    float ax = 0.f, ay = 0.f, az = 0.f, aw = 0.f;
#pragma unroll
    for (int k = 0; k < 16; k++) {
        float4 wv = w[k * 32 + lane];
        float4 hv = sh[k * 32 + lane];
        ax += wv.x * hv.x; ay += wv.y * hv.y;
        az += wv.z * hv.z; aw += wv.w * hv.w;
    }
    return wreduce((ax + ay) + (az + aw));
}

// ---------------- kernel 0: fp32 -> fp16 weight conversion -------------------
__global__ void cvt_kernel(const float* __restrict__ A,
                           const float* __restrict__ B,
                           const float* __restrict__ C) {
    size_t n4 = WELEM / 4;
    size_t stride = (size_t)gridDim.x * blockDim.x;
    for (size_t i = (size_t)blockIdx.x * blockDim.x + threadIdx.x; i < n4; i += stride) {
        float4 a = ((const float4*)A)[i];
        float4 b = ((const float4*)B)[i];
        float4 c = ((const float4*)C)[i];
        ((__half2*)g_whh1)[2*i]   = __floats2half2_rn(a.x, a.y);
        ((__half2*)g_whh1)[2*i+1] = __floats2half2_rn(a.z, a.w);
        ((__half2*)g_wih2)[2*i]   = __floats2half2_rn(b.x, b.y);
        ((__half2*)g_wih2)[2*i+1] = __floats2half2_rn(b.z, b.w);
        ((__half2*)g_whh2)[2*i]   = __floats2half2_rn(c.x, c.y);
        ((__half2*)g_whh2)[2*i+1] = __floats2half2_rn(c.z, c.w);
    }
}

// ---------------- kernel 1: pre1[t][row] = b1 + W_ih1[row,:] @ y[t,:] --------
__global__ void pre1_kernel(const float* __restrict__ y,
                            const float* __restrict__ W_ih1,
                            const float* __restrict__ b_ih1,
                            const float* __restrict__ b_hh1) {
    __shared__ float sy[64 * Dd];
    int row = blockIdx.x * 128 + threadIdx.x;
    int t0 = blockIdx.y * 64;
    for (int i = threadIdx.x; i < 64 * Dd; i += 128)
        sy[i] = y[(size_t)t0 * Dd + i];
    __syncthreads();

    float w[Dd];
#pragma unroll
    for (int k = 0; k < Dd; k++) w[k] = W_ih1[(size_t)row * Dd + k];
    float b = b_ih1[row] + b_hh1[row];

    for (int tt = 0; tt < 64; tt++) {
        float acc = b;
#pragma unroll
        for (int k = 0; k < Dd; k++) acc += w[k] * sy[tt * Dd + k];
        __stcs(&g_pre1[(size_t)(t0 + tt) * G4H + row], __float2half_rn(acc));
    }
}

// ---------------- kernel 2: persistent fused LSTM (1 barrier / step) ---------
// Phase t computes layer2[t] (needs h1[t], h2[t-1]) AND layer1[t+1] (needs
// h1[t] only) concurrently, then one barrier publishes h1[t+1] and h2[t].
__global__ void __launch_bounds__(NTHR, 1)
lstm_kernel(const float* __restrict__ b_ih2,
            const float* __restrict__ b_hh2) {
    __shared__ float sA[Hh];        // h1[t]
    __shared__ float sB[Hh];        // h2[t-1]
    __shared__ float sg1[64];       // W_hh1 @ h1 partials
    __shared__ float sg2[2][64];    // W_ih2@h1, W_hh2@h2 partials
    __shared__ float sbias[64];
    __shared__ float sc1[16];
    __shared__ float sc2[16];

    const int tid  = threadIdx.x;
    const int lane = tid & 31;
    const int warp = tid >> 5;
    const int b    = blockIdx.x;

    const int base  = Hh / NBLK;          // 13
    const int extra = Hh % NBLK;          // 124
    const int nj = base + (b < extra ? 1 : 0);
    const int j0 = b * base + (b < extra ? b : extra);

    unsigned bgen = g_release;

    // init: h2[-1]=0, c1=c2=0, layer-2 bias cache
    for (int j = tid; j < nj; j += NTHR) g_h2[0][j0 + j] = 0.f;
    for (int r = tid; r < 4 * nj; r += NTHR) {
        int j = r >> 2, q = r & 3;
        sbias[r] = b_ih2[q * Hh + j0 + j] + b_hh2[q * Hh + j0 + j];
    }
    if (tid < 16) { sc1[tid] = 0.f; sc2[tid] = 0.f; }
    __syncthreads();

    // prologue: h1[0] = cell1(x0, 0, 0)  (W_hh1 @ 0 == 0, so gates = pre1[0])
    if (tid < nj) {
        size_t pb = (size_t)j0 + tid;
        float gi = sigf (__half2float(__ldcs(&g_pre1[pb])));
        float gf = sigf (__half2float(__ldcs(&g_pre1[pb + Hh])));
        float gg = tanhf(__half2float(__ldcs(&g_pre1[pb + 2 * Hh])));
        float go = sigf (__half2float(__ldcs(&g_pre1[pb + 3 * Hh])));
        (void)gf;
        float c = gi * gg;
        sc1[tid] = c;
        g_h1[0][j0 + tid] = go * tanhf(c);
    }
    gbar(++bgen);

    for (int t = 0; t < Tt; t++) {
        const int p = t & 1;
        const bool last = (t == Tt - 1);

        for (int i = tid; i < Hh / 4; i += NTHR)
            ((float4*)sA)[i] = ((const float4*)g_h1[p])[i];
        for (int i = tid; i < Hh / 4; i += NTHR)
            ((float4*)sB)[i] = ((const float4*)g_h2[p])[i];
        __syncthreads();

        const int ntask = last ? 2 * nj : 3 * nj;
        for (int task = warp; task < ntask; task += NWARP) {
            const __half* wbase;
            const float4* hv;
            int m, j;
            if (task < nj)            { m = 0; j = task;          wbase = g_wih2; hv = (const float4*)sA; }
            else if (task < 2 * nj)   { m = 1; j = task - nj;     wbase = g_whh2; hv = (const float4*)sB; }
            else                      { m = 2; j = task - 2 * nj; wbase = g_whh1; hv = (const float4*)sA; }
            float4 r = dot4rows(wbase + (size_t)(j0 + j) * Hh, hv, lane);
            if (lane == 0) {
                float* dst = (m == 2) ? &sg1[j * 4] : &sg2[m][j * 4];
                dst[0] = r.x; dst[1] = r.y; dst[2] = r.z; dst[3] = r.w;
            }
        }
        __syncthreads();

        if (tid < nj) {
            // layer-2 update -> h2[t]
            float gi = sigf (sg2[0][tid*4+0] + sg2[1][tid*4+0] + sbias[tid*4+0]);
            float gf = sigf (sg2[0][tid*4+1] + sg2[1][tid*4+1] + sbias[tid*4+1]);
            float gg = tanhf(sg2[0][tid*4+2] + sg2[1][tid*4+2] + sbias[tid*4+2]);
            float go = sigf (sg2[0][tid*4+3] + sg2[1][tid*4+3] + sbias[tid*4+3]);
            float c = gf * sc2[tid] + gi * gg;
            sc2[tid] = c;
            float hn = go * tanhf(c);
            g_h2[1 - p][j0 + tid] = hn;
            __stcs(&g_h2hist[t][j0 + tid], hn);
        } else if (tid >= 32 && tid < 32 + nj && !last) {
            // layer-1 update -> h1[t+1]
            int u = tid - 32;
            size_t pb = (size_t)(t + 1) * G4H + j0 + u;
            float gi = sigf (sg1[u*4+0] + __half2float(__ldcs(&g_pre1[pb])));
            float gf = sigf (sg1[u*4+1] + __half2float(__ldcs(&g_pre1[pb + Hh])));
            float gg = tanhf(sg1[u*4+2] + __half2float(__ldcs(&g_pre1[pb + 2 * Hh])));
            float go = sigf (sg1[u*4+3] + __half2float(__ldcs(&g_pre1[pb + 3 * Hh])));
            float c = gf * sc1[u] + gi * gg;
            sc1[u] = c;
            g_h1[1 - p][j0 + u] = go * tanhf(c);
        }
        gbar(++bgen);
    }
}

// ---------------- kernel 3: output projection --------------------------------
__global__ void proj_kernel(const float* __restrict__ W_lin,
                            const float* __restrict__ b_lin,
                            float* __restrict__ out,
                            int prelen) {
    __shared__ float sh[Hh];
    const int t = prelen + blockIdx.x;
    const int tid = threadIdx.x;
    const int lane = tid & 31;
    const int warp = tid >> 5;

    for (int i = tid; i < Hh / 4; i += 256)
        ((float4*)sh)[i] = ((const float4*)&g_h2hist[t][0])[i];
    __syncthreads();

    for (int d = warp; d < Dd; d += 8) {
        float s = warp_dot((const float4*)(W_lin + (size_t)d * Hh),
                           (const float4*)sh, lane);
        if (lane == 0) out[(size_t)blockIdx.x * Dd + d] = s + b_lin[d];
    }
}

extern "C" void kernel_launch(void* const* d_in, const int* in_sizes, int n_in,
                              void* d_out, int out_size) {
    const float* y     = (const float*)d_in[0];
    const float* W_ih1 = (const float*)d_in[1];
    const float* W_hh1 = (const float*)d_in[2];
    const float* b_ih1 = (const float*)d_in[3];
    const float* b_hh1 = (const float*)d_in[4];
    const float* W_ih2 = (const float*)d_in[5];
    const float* W_hh2 = (const float*)d_in[6];
    const float* b_ih2 = (const float*)d_in[7];
    const float* b_hh2 = (const float*)d_in[8];
    const float* W_lin = (const float*)d_in[9];
    const float* b_lin = (const float*)d_in[10];
    (void)in_sizes; (void)n_in;

    const int nt = out_size / Dd;
    const int prelen = Tt - nt;

    cvt_kernel<<<2048, 256>>>(W_hh1, W_ih2, W_hh2);
    dim3 g1(G4H / 128, Tt / 64);
    pre1_kernel<<<g1, 128>>>(y, W_ih1, b_ih1, b_hh1);
    lstm_kernel<<<NBLK, NTHR>>>(b_ih2, b_hh2);
    proj_kernel<<<nt, 256>>>(W_lin, b_lin, (float*)d_out, prelen);
}

// round 5
// speedup vs baseline: 1.6068x; 1.6068x over previous
#include <cuda_runtime.h>
#include <cuda_fp16.h>
#include <math.h>

#define Hh 2048
#define Tt 4096
#define Dd 66
#define G4H (4*Hh)
#define NBLK 148
#define NTHR 512
#define NWARP (NTHR/32)
#define WELEM ((size_t)G4H*(size_t)Hh)
#define WSTRIDE ((size_t)Hh*(size_t)Hh)

// ---------------- persistent device state (static; no runtime allocs) -------
__device__ float  g_h1[2][Hh];
__device__ float  g_h2[2][Hh];
__device__ float  g_h2hist[Tt][Hh];                // 33.5 MB
__device__ __half g_pre1[(size_t)Tt * G4H];        // 67 MB fp16 (streamed, .cs)
__device__ __half g_whh1[WELEM];                   // 33.5 MB fp16 (L2-resident)
__device__ __half g_wih2[WELEM];
__device__ __half g_whh2[WELEM];

// flag barrier state (monotonic across graph replays)
__device__ volatile unsigned g_arrive[NBLK];
__device__ volatile unsigned g_release;

__device__ __forceinline__ float sigf(float x) { return 1.0f / (1.0f + expf(-x)); }

// ---------------- flag-based grid barrier -----------------------------------
__device__ __forceinline__ void gbar(unsigned target) {
    __syncthreads();
    if (blockIdx.x == 0) {
        if (threadIdx.x > 0 && threadIdx.x < NBLK) {
            while ((int)(g_arrive[threadIdx.x] - target) < 0) { }
        }
        __syncthreads();
        if (threadIdx.x == 0) { __threadfence(); g_release = target; }
    } else {
        if (threadIdx.x == 0) {
            __threadfence();
            g_arrive[blockIdx.x] = target;
            while ((int)(g_release - target) < 0) { }
            __threadfence();
        }
    }
    __syncthreads();
}

// ---------------- helpers ----------------------------------------------------
__device__ __forceinline__ float wreduce(float s) {
#pragma unroll
    for (int o = 16; o; o >>= 1) s += __shfl_down_sync(0xffffffffu, s, o);
    return s;
}

__device__ __forceinline__ float cvdot(uint2 u, float4 h) {
    float2 f0 = __half22float2(*reinterpret_cast<__half2*>(&u.x));
    float2 f1 = __half22float2(*reinterpret_cast<__half2*>(&u.y));
    return f0.x * h.x + f0.y * h.y + f1.x * h.z + f1.y * h.w;
}

// Dot of 4 fp16 weight rows (gates i/f/g/o of one hidden unit) against one
// fp32 vector in smem. unroll 4 (R2-proven register footprint).
__device__ __forceinline__ float4 dot4rows(const __half* __restrict__ w0,
                                           const float4* __restrict__ hv,
                                           int lane) {
    const __half* w1 = w0 + WSTRIDE;
    const __half* w2 = w0 + 2 * WSTRIDE;
    const __half* w3 = w0 + 3 * WSTRIDE;
    float a0 = 0.f, a1 = 0.f, a2 = 0.f, a3 = 0.f;
#pragma unroll 4
    for (int k = 0; k < 16; k++) {
        int idx = k * 32 + lane;
        float4 h = hv[idx];
        a0 += cvdot(((const uint2*)w0)[idx], h);
        a1 += cvdot(((const uint2*)w1)[idx], h);
        a2 += cvdot(((const uint2*)w2)[idx], h);
        a3 += cvdot(((const uint2*)w3)[idx], h);
    }
    return make_float4(wreduce(a0), wreduce(a1), wreduce(a2), wreduce(a3));
}

// fp32 warp dot (proj kernel only)
__device__ __forceinline__ float warp_dot(const float4* __restrict__ w,
                                          const float4* __restrict__ sh,
                                          int lane) {
    float ax = 0.f, ay = 0.f, az = 0.f, aw = 0.f;
#pragma unroll
    for (int k = 0; k < 16; k++) {
        float4 wv = w[k * 32 + lane];
        float4 hv = sh[k * 32 + lane];
        ax += wv.x * hv.x; ay += wv.y * hv.y;
        az += wv.z * hv.z; aw += wv.w * hv.w;
    }
    return wreduce((ax + ay) + (az + aw));
}

// ---------------- kernel 0: fp32 -> fp16 weight conversion -------------------
__global__ void cvt_kernel(const float* __restrict__ A,
                           const float* __restrict__ B,
                           const float* __restrict__ C) {
    size_t n4 = WELEM / 4;
    size_t stride = (size_t)gridDim.x * blockDim.x;
    for (size_t i = (size_t)blockIdx.x * blockDim.x + threadIdx.x; i < n4; i += stride) {
        float4 a = ((const float4*)A)[i];
        float4 b = ((const float4*)B)[i];
        float4 c = ((const float4*)C)[i];
        ((__half2*)g_whh1)[2*i]   = __floats2half2_rn(a.x, a.y);
        ((__half2*)g_whh1)[2*i+1] = __floats2half2_rn(a.z, a.w);
        ((__half2*)g_wih2)[2*i]   = __floats2half2_rn(b.x, b.y);
        ((__half2*)g_wih2)[2*i+1] = __floats2half2_rn(b.z, b.w);
        ((__half2*)g_whh2)[2*i]   = __floats2half2_rn(c.x, c.y);
        ((__half2*)g_whh2)[2*i+1] = __floats2half2_rn(c.z, c.w);
    }
}

// ---------------- kernel 1: pre1[t][row] = b1 + W_ih1[row,:] @ y[t,:] --------
__global__ void pre1_kernel(const float* __restrict__ y,
                            const float* __restrict__ W_ih1,
                            const float* __restrict__ b_ih1,
                            const float* __restrict__ b_hh1) {
    __shared__ float sy[64 * Dd];
    int row = blockIdx.x * 128 + threadIdx.x;
    int t0 = blockIdx.y * 64;
    for (int i = threadIdx.x; i < 64 * Dd; i += 128)
        sy[i] = y[(size_t)t0 * Dd + i];
    __syncthreads();

    float w[Dd];
#pragma unroll
    for (int k = 0; k < Dd; k++) w[k] = W_ih1[(size_t)row * Dd + k];
    float b = b_ih1[row] + b_hh1[row];

    for (int tt = 0; tt < 64; tt++) {
        float acc = b;
#pragma unroll
        for (int k = 0; k < Dd; k++) acc += w[k] * sy[tt * Dd + k];
        __stcs(&g_pre1[(size_t)(t0 + tt) * G4H + row], __float2half_rn(acc));
    }
}

// ---------------- kernel 2: persistent fused LSTM (1 barrier / step) ---------
// Phase t computes layer2[t] (h1[t], h2[t-1]) AND layer1[t+1] (h1[t] only)
// concurrently; one barrier publishes h1[t+1], h2[t]. pre1[t+1] is prefetched
// into smem at phase start so its DRAM latency hides under the dot rounds.
__global__ void __launch_bounds__(NTHR, 1)
lstm_kernel(const float* __restrict__ b_ih2,
            const float* __restrict__ b_hh2) {
    __shared__ float sA[Hh];        // h1[t]
    __shared__ float sB[Hh];        // h2[t-1]
    __shared__ float sg1[64];       // W_hh1 @ h1 partials
    __shared__ float sg2[2][64];    // W_ih2@h1, W_hh2@h2 partials
    __shared__ float sbias[64];
    __shared__ float spre[64];      // pre1[t+1] prefetch
    __shared__ float sc1[16];
    __shared__ float sc2[16];

    const int tid  = threadIdx.x;
    const int lane = tid & 31;
    const int warp = tid >> 5;
    const int b    = blockIdx.x;

    const int base  = Hh / NBLK;          // 13
    const int extra = Hh % NBLK;          // 124
    const int nj = base + (b < extra ? 1 : 0);
    const int j0 = b * base + (b < extra ? b : extra);

    unsigned bgen = g_release;

    // init: h2[-1]=0, c1=c2=0, layer-2 bias cache
    for (int j = tid; j < nj; j += NTHR) g_h2[0][j0 + j] = 0.f;
    for (int r = tid; r < 4 * nj; r += NTHR) {
        int j = r >> 2, q = r & 3;
        sbias[r] = b_ih2[q * Hh + j0 + j] + b_hh2[q * Hh + j0 + j];
    }
    if (tid < 16) { sc1[tid] = 0.f; sc2[tid] = 0.f; }
    __syncthreads();

    // prologue: h1[0] = cell1(x0, 0, 0)   (gates = pre1[0])
    if (tid < nj) {
        size_t pb = (size_t)j0 + tid;
        float gi = sigf (__half2float(__ldcs(&g_pre1[pb])));
        float gg = tanhf(__half2float(__ldcs(&g_pre1[pb + 2 * Hh])));
        float go = sigf (__half2float(__ldcs(&g_pre1[pb + 3 * Hh])));
        float c = gi * gg;
        sc1[tid] = c;
        g_h1[0][j0 + tid] = go * tanhf(c);
    }
    gbar(++bgen);

    for (int t = 0; t < Tt; t++) {
        const int p = t & 1;
        const bool last = (t == Tt - 1);

        // prefetch pre1[t+1] (4 coalesced ~28B segments), latency hidden
        if (!last && tid < 64) {
            int q = tid >> 4, jj = tid & 15;
            if (jj < nj)
                spre[jj * 4 + q] = __half2float(
                    __ldcs(&g_pre1[(size_t)(t + 1) * G4H + q * Hh + j0 + jj]));
        }
        for (int i = tid; i < Hh / 4; i += NTHR)
            ((float4*)sA)[i] = ((const float4*)g_h1[p])[i];
        for (int i = tid; i < Hh / 4; i += NTHR)
            ((float4*)sB)[i] = ((const float4*)g_h2[p])[i];
        __syncthreads();

        const int ntask = last ? 2 * nj : 3 * nj;
        for (int task = warp; task < ntask; task += NWARP) {
            const __half* wbase;
            const float4* hv;
            int m, j;
            if (task < nj)            { m = 0; j = task;          wbase = g_wih2; hv = (const float4*)sA; }
            else if (task < 2 * nj)   { m = 1; j = task - nj;     wbase = g_whh2; hv = (const float4*)sB; }
            else                      { m = 2; j = task - 2 * nj; wbase = g_whh1; hv = (const float4*)sA; }
            float4 r = dot4rows(wbase + (size_t)(j0 + j) * Hh, hv, lane);
            if (lane == 0) {
                float* dst = (m == 2) ? &sg1[j * 4] : &sg2[m][j * 4];
                dst[0] = r.x; dst[1] = r.y; dst[2] = r.z; dst[3] = r.w;
            }
        }
        __syncthreads();

        if (tid < nj) {
            // layer-2 update -> h2[t]
            float gi = sigf (sg2[0][tid*4+0] + sg2[1][tid*4+0] + sbias[tid*4+0]);
            float gf = sigf (sg2[0][tid*4+1] + sg2[1][tid*4+1] + sbias[tid*4+1]);
            float gg = tanhf(sg2[0][tid*4+2] + sg2[1][tid*4+2] + sbias[tid*4+2]);
            float go = sigf (sg2[0][tid*4+3] + sg2[1][tid*4+3] + sbias[tid*4+3]);
            float c = gf * sc2[tid] + gi * gg;
            sc2[tid] = c;
            float hn = go * tanhf(c);
            g_h2[1 - p][j0 + tid] = hn;
            __stcs(&g_h2hist[t][j0 + tid], hn);
        } else if (tid >= 32 && tid < 32 + nj && !last) {
            // layer-1 update -> h1[t+1]  (pre1 already staged in smem)
            int u = tid - 32;
            float gi = sigf (sg1[u*4+0] + spre[u*4+0]);
            float gf = sigf (sg1[u*4+1] + spre[u*4+1]);
            float gg = tanhf(sg1[u*4+2] + spre[u*4+2]);
            float go = sigf (sg1[u*4+3] + spre[u*4+3]);
            float c = gf * sc1[u] + gi * gg;
            sc1[u] = c;
            g_h1[1 - p][j0 + u] = go * tanhf(c);
        }
        gbar(++bgen);
    }
}

// ---------------- kernel 3: output projection --------------------------------
__global__ void proj_kernel(const float* __restrict__ W_lin,
                            const float* __restrict__ b_lin,
                            float* __restrict__ out,
                            int prelen) {
    __shared__ float sh[Hh];
    const int t = prelen + blockIdx.x;
    const int tid = threadIdx.x;
    const int lane = tid & 31;
    const int warp = tid >> 5;

    for (int i = tid; i < Hh / 4; i += 256)
        ((float4*)sh)[i] = ((const float4*)&g_h2hist[t][0])[i];
    __syncthreads();

    for (int d = warp; d < Dd; d += 8) {
        float s = warp_dot((const float4*)(W_lin + (size_t)d * Hh),
                           (const float4*)sh, lane);
        if (lane == 0) out[(size_t)blockIdx.x * Dd + d] = s + b_lin[d];
    }
}

extern "C" void kernel_launch(void* const* d_in, const int* in_sizes, int n_in,
                              void* d_out, int out_size) {
    const float* y     = (const float*)d_in[0];
    const float* W_ih1 = (const float*)d_in[1];
    const float* W_hh1 = (const float*)d_in[2];
    const float* b_ih1 = (const float*)d_in[3];
    const float* b_hh1 = (const float*)d_in[4];
    const float* W_ih2 = (const float*)d_in[5];
    const float* W_hh2 = (const float*)d_in[6];
    const float* b_ih2 = (const float*)d_in[7];
    const float* b_hh2 = (const float*)d_in[8];
    const float* W_lin = (const float*)d_in[9];
    const float* b_lin = (const float*)d_in[10];
    (void)in_sizes; (void)n_in;

    const int nt = out_size / Dd;
    const int prelen = Tt - nt;

    cvt_kernel<<<2048, 256>>>(W_hh1, W_ih2, W_hh2);
    dim3 g1(G4H / 128, Tt / 64);
    pre1_kernel<<<g1, 128>>>(y, W_ih1, b_ih1, b_hh1);
    lstm_kernel<<<NBLK, NTHR>>>(b_ih2, b_hh2);
    proj_kernel<<<nt, 256>>>(W_lin, b_lin, (float*)d_out, prelen);
}

// round 6
// speedup vs baseline: 2.0852x; 1.2978x over previous
#include <cuda_runtime.h>
#include <cuda_fp16.h>
#include <math.h>

#define Hh 2048
#define Tt 4096
#define Dd 66
#define G4H (4*Hh)
#define NBLK 148
#define NTHR 512
#define NWARP (NTHR/32)
#define NJMAX 14
#define WELEM ((size_t)G4H*(size_t)Hh)
#define WSTRIDE ((size_t)Hh*(size_t)Hh)
#define SWBYTES (3*NJMAX*Hh*sizeof(__half))   // 172032 B pinned W_hh1 gates i,f,g

// ---------------- persistent device state (static; no runtime allocs) -------
__device__ float  g_h1[2][Hh];
__device__ float  g_h2[2][Hh];
__device__ float  g_h2hist[Tt][Hh];                // 33.5 MB
__device__ __half g_pre1[(size_t)Tt * G4H];        // 67 MB fp16 (streamed, .cs)
__device__ __half g_whh1[WELEM];                   // 33.5 MB fp16
__device__ __half g_wih2[WELEM];
__device__ __half g_whh2[WELEM];

// flag barrier state (monotonic across graph replays)
__device__ volatile unsigned g_arrive[NBLK];
__device__ volatile unsigned g_release;

__device__ __forceinline__ float sigf(float x) { return 1.0f / (1.0f + expf(-x)); }

// ---------------- flag-based grid barrier -----------------------------------
__device__ __forceinline__ void gbar(unsigned target) {
    __syncthreads();
    if (blockIdx.x == 0) {
        if (threadIdx.x > 0 && threadIdx.x < NBLK) {
            while ((int)(g_arrive[threadIdx.x] - target) < 0) { }
        }
        __syncthreads();
        if (threadIdx.x == 0) { __threadfence(); g_release = target; }
    } else {
        if (threadIdx.x == 0) {
            __threadfence();
            g_arrive[blockIdx.x] = target;
            while ((int)(g_release - target) < 0) { }
            __threadfence();
        }
    }
    __syncthreads();
}

// ---------------- helpers ----------------------------------------------------
__device__ __forceinline__ float wreduce(float s) {
#pragma unroll
    for (int o = 16; o; o >>= 1) s += __shfl_down_sync(0xffffffffu, s, o);
    return s;
}

// dot of one uint4 (8 fp16) with 8 fp32 h values
__device__ __forceinline__ float du4(uint4 u, float4 h0, float4 h1) {
    float2 a = __half22float2(*reinterpret_cast<__half2*>(&u.x));
    float2 b = __half22float2(*reinterpret_cast<__half2*>(&u.y));
    float2 c = __half22float2(*reinterpret_cast<__half2*>(&u.z));
    float2 d = __half22float2(*reinterpret_cast<__half2*>(&u.w));
    return a.x*h0.x + a.y*h0.y + b.x*h0.z + b.y*h0.w
         + c.x*h1.x + c.y*h1.y + d.x*h1.z + d.y*h1.w;
}

// 4 gate rows (i/f/g/o) all streaming from global (uint4, 16B/lane/row/iter)
__device__ __forceinline__ float4 dot4g(const __half* __restrict__ w0,
                                        const float4* __restrict__ hv, int lane) {
    const uint4* p0 = (const uint4*)w0;
    const uint4* p1 = (const uint4*)(w0 + WSTRIDE);
    const uint4* p2 = (const uint4*)(w0 + 2 * WSTRIDE);
    const uint4* p3 = (const uint4*)(w0 + 3 * WSTRIDE);
    float a0 = 0.f, a1 = 0.f, a2 = 0.f, a3 = 0.f;
#pragma unroll 2
    for (int k = 0; k < 8; k++) {
        int idx = k * 32 + lane;
        float4 h0 = hv[2 * idx], h1 = hv[2 * idx + 1];
        a0 += du4(p0[idx], h0, h1);
        a1 += du4(p1[idx], h0, h1);
        a2 += du4(p2[idx], h0, h1);
        a3 += du4(p3[idx], h0, h1);
    }
    return make_float4(wreduce(a0), wreduce(a1), wreduce(a2), wreduce(a3));
}

// gates i/f/g pinned in smem, gate o streaming from global
__device__ __forceinline__ float4 dot_pin(const __half* si, const __half* sf,
                                          const __half* sg,
                                          const __half* __restrict__ wo,
                                          const float4* __restrict__ hv, int lane) {
    const uint4* pi = (const uint4*)si;
    const uint4* pf = (const uint4*)sf;
    const uint4* pg = (const uint4*)sg;
    const uint4* po = (const uint4*)wo;
    float a0 = 0.f, a1 = 0.f, a2 = 0.f, a3 = 0.f;
#pragma unroll 2
    for (int k = 0; k < 8; k++) {
        int idx = k * 32 + lane;
        float4 h0 = hv[2 * idx], h1 = hv[2 * idx + 1];
        a0 += du4(pi[idx], h0, h1);
        a1 += du4(pf[idx], h0, h1);
        a2 += du4(pg[idx], h0, h1);
        a3 += du4(po[idx], h0, h1);
    }
    return make_float4(wreduce(a0), wreduce(a1), wreduce(a2), wreduce(a3));
}

// fp32 warp dot (proj kernel only)
__device__ __forceinline__ float warp_dot(const float4* __restrict__ w,
                                          const float4* __restrict__ sh,
                                          int lane) {
    float ax = 0.f, ay = 0.f, az = 0.f, aw = 0.f;
#pragma unroll
    for (int k = 0; k < 16; k++) {
        float4 wv = w[k * 32 + lane];
        float4 hv = sh[k * 32 + lane];
        ax += wv.x * hv.x; ay += wv.y * hv.y;
        az += wv.z * hv.z; aw += wv.w * hv.w;
    }
    return wreduce((ax + ay) + (az + aw));
}

// ---------------- kernel 0: fp32 -> fp16 weight conversion -------------------
__global__ void cvt_kernel(const float* __restrict__ A,
                           const float* __restrict__ B,
                           const float* __restrict__ C) {
    size_t n4 = WELEM / 4;
    size_t stride = (size_t)gridDim.x * blockDim.x;
    for (size_t i = (size_t)blockIdx.x * blockDim.x + threadIdx.x; i < n4; i += stride) {
        float4 a = ((const float4*)A)[i];
        float4 b = ((const float4*)B)[i];
        float4 c = ((const float4*)C)[i];
        ((__half2*)g_whh1)[2*i]   = __floats2half2_rn(a.x, a.y);
        ((__half2*)g_whh1)[2*i+1] = __floats2half2_rn(a.z, a.w);
        ((__half2*)g_wih2)[2*i]   = __floats2half2_rn(b.x, b.y);
        ((__half2*)g_wih2)[2*i+1] = __floats2half2_rn(b.z, b.w);
        ((__half2*)g_whh2)[2*i]   = __floats2half2_rn(c.x, c.y);
        ((__half2*)g_whh2)[2*i+1] = __floats2half2_rn(c.z, c.w);
    }
}

// ---------------- kernel 1: pre1[t][row] = b1 + W_ih1[row,:] @ y[t,:] --------
__global__ void pre1_kernel(const float* __restrict__ y,
                            const float* __restrict__ W_ih1,
                            const float* __restrict__ b_ih1,
                            const float* __restrict__ b_hh1) {
    __shared__ float sy[64 * Dd];
    int row = blockIdx.x * 128 + threadIdx.x;
    int t0 = blockIdx.y * 64;
    for (int i = threadIdx.x; i < 64 * Dd; i += 128)
        sy[i] = y[(size_t)t0 * Dd + i];
    __syncthreads();

    float w[Dd];
#pragma unroll
    for (int k = 0; k < Dd; k++) w[k] = W_ih1[(size_t)row * Dd + k];
    float b = b_ih1[row] + b_hh1[row];

    for (int tt = 0; tt < 64; tt++) {
        float acc = b;
#pragma unroll
        for (int k = 0; k < Dd; k++) acc += w[k] * sy[tt * Dd + k];
        __stcs(&g_pre1[(size_t)(t0 + tt) * G4H + row], __float2half_rn(acc));
    }
}

// ---------------- kernel 2: persistent fused LSTM (1 barrier / step) ---------
// W_hh1 gates i/f/g for this block's rows pinned in smem (preloaded once,
// reused 4096 steps). Phase t computes layer2[t] AND layer1[t+1]; one barrier.
__global__ void __launch_bounds__(NTHR, 1)
lstm_kernel(const float* __restrict__ b_ih2,
            const float* __restrict__ b_hh2) {
    extern __shared__ __half swei[];   // [3][nj][Hh]
    __shared__ float sA[Hh];        // h1[t]
    __shared__ float sB[Hh];        // h2[t-1]
    __shared__ float sg1[64];       // W_hh1 @ h1 partials
    __shared__ float sg2[2][64];    // W_ih2@h1, W_hh2@h2 partials
    __shared__ float sbias[64];
    __shared__ float spre[64];      // pre1[t+1] prefetch
    __shared__ float sc1[16];
    __shared__ float sc2[16];

    const int tid  = threadIdx.x;
    const int lane = tid & 31;
    const int warp = tid >> 5;
    const int b    = blockIdx.x;

    const int base  = Hh / NBLK;          // 13
    const int extra = Hh % NBLK;          // 124
    const int nj = base + (b < extra ? 1 : 0);
    const int j0 = b * base + (b < extra ? b : extra);

    unsigned bgen = g_release;

    // pin W_hh1 gates i,f,g rows into smem (coalesced uint4 copy, one-time)
    const int segs = Hh / 8;
    for (int i = tid; i < 3 * nj * segs; i += NTHR) {
        int row = i / segs;
        int seg = i - row * segs;
        int g = row / nj, j = row - g * nj;
        ((uint4*)swei)[(size_t)row * segs + seg] =
            ((const uint4*)(g_whh1 + ((size_t)g * Hh + j0 + j) * Hh))[seg];
    }

    // init: h2[-1]=0, c1=c2=0, layer-2 bias cache
    for (int j = tid; j < nj; j += NTHR) g_h2[0][j0 + j] = 0.f;
    for (int r = tid; r < 4 * nj; r += NTHR) {
        int j = r >> 2, q = r & 3;
        sbias[r] = b_ih2[q * Hh + j0 + j] + b_hh2[q * Hh + j0 + j];
    }
    if (tid < 16) { sc1[tid] = 0.f; sc2[tid] = 0.f; }
    __syncthreads();

    // prologue: h1[0] = cell1(x0, 0, 0)   (gates = pre1[0])
    if (tid < nj) {
        size_t pb = (size_t)j0 + tid;
        float gi = sigf (__half2float(__ldcs(&g_pre1[pb])));
        float gg = tanhf(__half2float(__ldcs(&g_pre1[pb + 2 * Hh])));
        float go = sigf (__half2float(__ldcs(&g_pre1[pb + 3 * Hh])));
        float c = gi * gg;
        sc1[tid] = c;
        g_h1[0][j0 + tid] = go * tanhf(c);
    }
    gbar(++bgen);

    for (int t = 0; t < Tt; t++) {
        const int p = t & 1;
        const bool last = (t == Tt - 1);

        // prefetch pre1[t+1] (latency hidden under dot rounds)
        if (!last && tid < 64) {
            int q = tid >> 4, jj = tid & 15;
            if (jj < nj)
                spre[jj * 4 + q] = __half2float(
                    __ldcs(&g_pre1[(size_t)(t + 1) * G4H + q * Hh + j0 + jj]));
        }
        for (int i = tid; i < Hh / 4; i += NTHR)
            ((float4*)sA)[i] = ((const float4*)g_h1[p])[i];
        for (int i = tid; i < Hh / 4; i += NTHR)
            ((float4*)sB)[i] = ((const float4*)g_h2[p])[i];
        __syncthreads();

        const int ntask = last ? 2 * nj : 3 * nj;
        for (int task = warp; task < ntask; task += NWARP) {
            if (task < 2 * nj) {
                int m = (task >= nj);
                int j = task - m * nj;
                const __half* wbase = m ? g_whh2 : g_wih2;
                const float4* hv = m ? (const float4*)sB : (const float4*)sA;
                float4 r = dot4g(wbase + (size_t)(j0 + j) * Hh, hv, lane);
                if (lane == 0) {
                    float* dst = &sg2[m][j * 4];
                    dst[0] = r.x; dst[1] = r.y; dst[2] = r.z; dst[3] = r.w;
                }
            } else {
                int j = task - 2 * nj;
                float4 r = dot_pin(swei + (size_t)j * Hh,
                                   swei + (size_t)(nj + j) * Hh,
                                   swei + (size_t)(2 * nj + j) * Hh,
                                   g_whh1 + ((size_t)3 * Hh + j0 + j) * Hh,
                                   (const float4*)sA, lane);
                if (lane == 0) {
                    sg1[j * 4 + 0] = r.x; sg1[j * 4 + 1] = r.y;
                    sg1[j * 4 + 2] = r.z; sg1[j * 4 + 3] = r.w;
                }
            }
        }
        __syncthreads();

        if (tid < nj) {
            // layer-2 update -> h2[t]
            float gi = sigf (sg2[0][tid*4+0] + sg2[1][tid*4+0] + sbias[tid*4+0]);
            float gf = sigf (sg2[0][tid*4+1] + sg2[1][tid*4+1] + sbias[tid*4+1]);
            float gg = tanhf(sg2[0][tid*4+2] + sg2[1][tid*4+2] + sbias[tid*4+2]);
            float go = sigf (sg2[0][tid*4+3] + sg2[1][tid*4+3] + sbias[tid*4+3]);
            float c = gf * sc2[tid] + gi * gg;
            sc2[tid] = c;
            float hn = go * tanhf(c);
            g_h2[1 - p][j0 + tid] = hn;
            __stcs(&g_h2hist[t][j0 + tid], hn);
        } else if (tid >= 32 && tid < 32 + nj && !last) {
            // layer-1 update -> h1[t+1]  (pre1 staged in smem)
            int u = tid - 32;
            float gi = sigf (sg1[u*4+0] + spre[u*4+0]);
            float gf = sigf (sg1[u*4+1] + spre[u*4+1]);
            float gg = tanhf(sg1[u*4+2] + spre[u*4+2]);
            float go = sigf (sg1[u*4+3] + spre[u*4+3]);
            float c = gf * sc1[u] + gi * gg;
            sc1[u] = c;
            g_h1[1 - p][j0 + u] = go * tanhf(c);
        }
        gbar(++bgen);
    }
}

// ---------------- kernel 3: output projection --------------------------------
__global__ void proj_kernel(const float* __restrict__ W_lin,
                            const float* __restrict__ b_lin,
                            float* __restrict__ out,
                            int prelen) {
    __shared__ float sh[Hh];
    const int t = prelen + blockIdx.x;
    const int tid = threadIdx.x;
    const int lane = tid & 31;
    const int warp = tid >> 5;

    for (int i = tid; i < Hh / 4; i += 256)
        ((float4*)sh)[i] = ((const float4*)&g_h2hist[t][0])[i];
    __syncthreads();

    for (int d = warp; d < Dd; d += 8) {
        float s = warp_dot((const float4*)(W_lin + (size_t)d * Hh),
                           (const float4*)sh, lane);
        if (lane == 0) out[(size_t)blockIdx.x * Dd + d] = s + b_lin[d];
    }
}

extern "C" void kernel_launch(void* const* d_in, const int* in_sizes, int n_in,
                              void* d_out, int out_size) {
    const float* y     = (const float*)d_in[0];
    const float* W_ih1 = (const float*)d_in[1];
    const float* W_hh1 = (const float*)d_in[2];
    const float* b_ih1 = (const float*)d_in[3];
    const float* b_hh1 = (const float*)d_in[4];
    const float* W_ih2 = (const float*)d_in[5];
    const float* W_hh2 = (const float*)d_in[6];
    const float* b_ih2 = (const float*)d_in[7];
    const float* b_hh2 = (const float*)d_in[8];
    const float* W_lin = (const float*)d_in[9];
    const float* b_lin = (const float*)d_in[10];
    (void)in_sizes; (void)n_in;

    const int nt = out_size / Dd;
    const int prelen = Tt - nt;

    cudaFuncSetAttribute(lstm_kernel,
                         cudaFuncAttributeMaxDynamicSharedMemorySize,
                         (int)SWBYTES);

    cvt_kernel<<<2048, 256>>>(W_hh1, W_ih2, W_hh2);
    dim3 g1(G4H / 128, Tt / 64);
    pre1_kernel<<<g1, 128>>>(y, W_ih1, b_ih1, b_hh1);
    lstm_kernel<<<NBLK, NTHR, SWBYTES>>>(b_ih2, b_hh2);
    proj_kernel<<<nt, 256>>>(W_lin, b_lin, (float*)d_out, prelen);
}